// round 11
// baseline (speedup 1.0000x reference)
#include <cuda_runtime.h>
#include <cstdint>

#define NUM_TOKENS 8192
#define HIDDEN 4096
#define NUM_EXPERTS 8
#define INTER 2048
#define GU_COLS 4096
#define MAX_TILES 72
#define NSTAGE 3

// ---------------- scratch ----------------
__device__ int g_counts[NUM_EXPERTS];
__device__ int g_lists[NUM_EXPERTS][NUM_TOKENS];
__device__ int g_is64;
// fragment-packed activations: [tile128][kfrag][mfrag 8][128 floats]
__device__ float g_xpack[(size_t)MAX_TILES * (HIDDEN / 8) * 8 * 128];
__device__ float g_interp[(size_t)MAX_TILES * (INTER / 8) * 8 * 128];

// ---------------- helpers ----------------
__device__ __forceinline__ uint32_t f2tf(float f) {
    uint32_t r;
    asm("cvt.rna.tf32.f32 %0, %1;" : "=r"(r) : "f"(f));
    return r;
}
__device__ __forceinline__ float4 cvt4(float4 v) {
    float4 r;
    r.x = __uint_as_float(f2tf(v.x));
    r.y = __uint_as_float(f2tf(v.y));
    r.z = __uint_as_float(f2tf(v.z));
    r.w = __uint_as_float(f2tf(v.w));
    return r;
}
__device__ __forceinline__ uint32_t smem_u32(const void* p) {
    uint32_t a;
    asm("{ .reg .u64 t; cvta.to.shared.u64 t, %1; cvt.u32.u64 %0, t; }" : "=r"(a) : "l"(p));
    return a;
}
__device__ __forceinline__ void mma8(float* d, const uint32_t* a, uint32_t b0, uint32_t b1) {
    asm volatile(
        "mma.sync.aligned.m16n8k8.row.col.f32.tf32.tf32.f32 "
        "{%0,%1,%2,%3},{%4,%5,%6,%7},{%8,%9},{%0,%1,%2,%3};"
        : "+f"(d[0]), "+f"(d[1]), "+f"(d[2]), "+f"(d[3])
        : "r"(a[0]), "r"(a[1]), "r"(a[2]), "r"(a[3]), "r"(b0), "r"(b1));
}
__device__ __forceinline__ void cpa16(uint32_t dst, const void* src, int srcsize) {
    asm volatile("cp.async.cg.shared.global [%0], [%1], 16, %2;" :: "r"(dst), "l"(src), "r"(srcsize));
}
__device__ __forceinline__ void cpa_commit() { asm volatile("cp.async.commit_group;" ::: "memory"); }
__device__ __forceinline__ void cpa_wait1()  { asm volatile("cp.async.wait_group 1;" ::: "memory"); }
__device__ __forceinline__ void cpa_wait0()  { asm volatile("cp.async.wait_group 0;" ::: "memory"); }

__device__ __forceinline__ float silu(float g) { return g / (1.0f + __expf(-g)); }

__device__ __forceinline__ int find_tile(int t, int* e_out, int* m0_out, int* cnt_out) {
    int acc = 0;
#pragma unroll
    for (int e = 0; e < NUM_EXPERTS; e++) {
        int c = g_counts[e];
        int nt = (c + 127) >> 7;
        if (t < acc + nt) { *e_out = e; *m0_out = (t - acc) << 7; *cnt_out = c; return 1; }
        acc += nt;
    }
    return 0;
}

// ---------------- routing ----------------
__global__ void detect_kernel(const int* __restrict__ t32) {
    if (threadIdx.x == 0) {
        int all_zero = 1;
        for (int i = 0; i < 256; i++) {
            int idx = 2 * (i * (NUM_TOKENS / 256)) + 1;
            if (t32[idx] != 0) { all_zero = 0; break; }
        }
        g_is64 = all_zero;
    }
    if (threadIdx.x < NUM_EXPERTS) g_counts[threadIdx.x] = 0;
}

__global__ void route_kernel(const int* __restrict__ t32) {
    int i = blockIdx.x * blockDim.x + threadIdx.x;
    if (i < NUM_TOKENS) {
        int v = g_is64 ? t32[2 * i] : t32[i];
        int e = v & 7;
        int p = atomicAdd(&g_counts[e], 1);
        g_lists[e][p] = i;
    }
}

// ---------------- pack_x: gather routed tokens -> tf32 fragment layout ----------------
#define PX_PITCH 132
#define PX_SMEM (128 * PX_PITCH * 4 + 512)
__global__ __launch_bounds__(256) void pack_x_kernel(const float* __restrict__ x) {
    extern __shared__ char smem[];
    int e, m0, count;
    if (!find_tile(blockIdx.y, &e, &m0, &count)) return;
    const int kb = blockIdx.x;
    const int tid = threadIdx.x;
    int* tokS = (int*)smem;
    float* tile = (float*)(smem + 512);
    if (tid < 128) tokS[tid] = (m0 + tid < count) ? g_lists[e][m0 + tid] : -1;
    __syncthreads();
#pragma unroll
    for (int j = 0; j < 16; j++) {
        int idx = tid + j * 256;
        int r = idx >> 5, c4 = (idx & 31) * 4;
        int t = tokS[r];
        float4 v = make_float4(0.f, 0.f, 0.f, 0.f);
        if (t >= 0) v = *(const float4*)(x + (size_t)t * HIDDEN + kb * 128 + c4);
        *(float4*)(tile + r * PX_PITCH + c4) = cvt4(v);
    }
    __syncthreads();
    const int lane = tid & 31, w = tid >> 5;
    const int g = lane >> 2, tq = lane & 3;
#pragma unroll
    for (int i = 0; i < 16; i++) {
        int f = w * 16 + i;
        int mf = f & 7, kfl = f >> 3;
        const float* src = tile + (mf * 16 + g) * PX_PITCH + kfl * 8 + tq;
        float4 o;
        o.x = src[0];
        o.y = src[8 * PX_PITCH];
        o.z = src[4];
        o.w = src[8 * PX_PITCH + 4];
        size_t off = (((size_t)blockIdx.y * (HIDDEN / 8) + kb * 16 + kfl) * 8 + mf) * 128 + lane * 4;
        *(float4*)(g_xpack + off) = o;
    }
}

// smem geometry: B-only ring
#define BPITCH 72
#define BPITCH2 136
#define B1_BYTES (32 * BPITCH * 4)        /* 9216  */
#define G1_STAGE (2 * B1_BYTES)           /* 18432 */
#define G2_STAGE (32 * BPITCH2 * 4)       /* 17408 */
#define G1_SMEM (NSTAGE * G1_STAGE)       /* 55296 */
#define G2_SMEM (NSTAGE * G2_STAGE)       /* 52224 */

// ---------------- GEMM1: Xpack(LDG) @ GU(smem) -> silu(gate)*up -> g_interp ----------------
// CTA = 128 threads (4 warps, 1m x 4n), BM=64 (half of a packed 128-tile), BN=64.
__global__ __launch_bounds__(128, 4) void gemm1_tc(const float* __restrict__ gup) {
    extern __shared__ char smem[];
    int e, m0, count;
    const int t128 = blockIdx.x >> 1;
    const int half = blockIdx.x & 1;
    if (!find_tile(t128, &e, &m0, &count)) return;
    const int n0 = blockIdx.y * 64;

    const uint32_t sb = smem_u32(smem);
    const int tid = threadIdx.x;
    const int nw = tid >> 5, lane = tid & 31;
    const int g = lane >> 2, tq = lane & 3;

    // A: packed tf32 fragments, warp-shared LDG.128
    const float* ap = g_xpack + (size_t)t128 * (HIDDEN / 8) * 1024
                              + (half * 4) * 128 + lane * 4;
    const float* Bx = gup + (size_t)e * HIDDEN * GU_COLS + n0;

    auto issue_B = [&](int kc, int soff) {
#pragma unroll
        for (int h = 0; h < 4; h++) {
            int idx = tid + h * 128;               // 512 over 32 rows x 16 float4
            int k = idx >> 4, n16 = (idx & 15) * 16;
            const float* gp = Bx + (size_t)(kc * 32 + k) * GU_COLS + (idx & 15) * 4;
            uint32_t base = sb + soff + k * (BPITCH * 4) + n16;
            cpa16(base, gp, 16);
            cpa16(base + B1_BYTES, gp + INTER, 16);
        }
    };

    float accg[4][2][4] = {};
    float accu[4][2][4] = {};

    issue_B(0, 0);
    cpa_commit();
    issue_B(1, G1_STAGE);
    cpa_commit();

    const int bfrag = tq * BPITCH + nw * 16 + g;

    const int NK = HIDDEN / 32;
    int soff_c = 0, soff_p = 2 * G1_STAGE;
    for (int kc = 0; kc < NK; kc++) {
        if (kc + 1 < NK) cpa_wait1(); else cpa_wait0();
        __syncthreads();
        if (kc + 2 < NK) {
            issue_B(kc + 2, soff_p);
            cpa_commit();
        }

        const float* Bg = (const float*)(smem + soff_c);
        const float* Bu = Bg + 32 * BPITCH;

#pragma unroll
        for (int kk = 0; kk < 4; kk++) {
            uint32_t bg[2][2], bu[2][2];
#pragma unroll
            for (int ni = 0; ni < 2; ni++) {
                const float* bp = Bg + kk * (8 * BPITCH) + bfrag + ni * 8;
                bg[ni][0] = f2tf(bp[0]); bg[ni][1] = f2tf(bp[4 * BPITCH]);
                const float* up = Bu + kk * (8 * BPITCH) + bfrag + ni * 8;
                bu[ni][0] = f2tf(up[0]); bu[ni][1] = f2tf(up[4 * BPITCH]);
            }
#pragma unroll
            for (int mi = 0; mi < 4; mi++) {
                const float4 av = *(const float4*)(ap + kk * 1024 + mi * 128);
                uint32_t a[4];
                a[0] = __float_as_uint(av.x);
                a[1] = __float_as_uint(av.y);
                a[2] = __float_as_uint(av.z);
                a[3] = __float_as_uint(av.w);
                mma8(accg[mi][0], a, bg[0][0], bg[0][1]);
                mma8(accg[mi][1], a, bg[1][0], bg[1][1]);
                mma8(accu[mi][0], a, bu[0][0], bu[0][1]);
                mma8(accu[mi][1], a, bu[1][0], bu[1][1]);
            }
        }
        ap += 4096;
        soff_c += G1_STAGE; if (soff_c == NSTAGE * G1_STAGE) soff_c = 0;
        soff_p += G1_STAGE; if (soff_p == NSTAGE * G1_STAGE) soff_p = 0;
    }

    // fused epilogue -> fragment-packed g_interp (pad rows are zeros; no guard needed)
#pragma unroll
    for (int mi = 0; mi < 4; mi++) {
        int mf = half * 4 + mi;
#pragma unroll
        for (int ni = 0; ni < 2; ni++) {
            int c = nw * 16 + ni * 8 + 2 * tq;
            int kf = (n0 + c) >> 3;
            int hc2 = ((c >> 2) & 1) * 2;
            int tq0 = c & 3;
            float* base = g_interp + (((size_t)t128 * (INTER / 8) + kf) * 8 + mf) * 128;
            base[(g * 4 + tq0) * 4 + hc2] =
                __uint_as_float(f2tf(silu(accg[mi][ni][0]) * accu[mi][ni][0]));
            base[(g * 4 + tq0 + 1) * 4 + hc2] =
                __uint_as_float(f2tf(silu(accg[mi][ni][1]) * accu[mi][ni][1]));
            base[(g * 4 + tq0) * 4 + 1 + hc2] =
                __uint_as_float(f2tf(silu(accg[mi][ni][2]) * accu[mi][ni][2]));
            base[(g * 4 + tq0 + 1) * 4 + 1 + hc2] =
                __uint_as_float(f2tf(silu(accg[mi][ni][3]) * accu[mi][ni][3]));
        }
    }
}

// ---------------- GEMM2: g_interp(LDG) @ down(smem) -> out  (BM=64, BN=128) ----------------
__global__ __launch_bounds__(128, 4) void gemm2_tc(const float* __restrict__ down,
                                                   float* __restrict__ out) {
    extern __shared__ char smem[];
    __shared__ int tokS[64];
    int e, m0, count;
    const int t128 = blockIdx.x >> 1;
    const int half = blockIdx.x & 1;
    if (!find_tile(t128, &e, &m0, &count)) return;
    const int n0 = blockIdx.y * 128;

    const uint32_t sb = smem_u32(smem);
    const int tid = threadIdx.x;
    const int nw = tid >> 5, lane = tid & 31;
    const int g = lane >> 2, tq = lane & 3;

    if (tid < 64) {
        int r = m0 + half * 64 + tid;
        tokS[tid] = (r < count) ? g_lists[e][r] : -1;
    }
    __syncthreads();

    const float* ap = g_interp + (size_t)t128 * (INTER / 8) * 1024
                               + (half * 4) * 128 + lane * 4;
    const float* Bx = down + (size_t)e * INTER * HIDDEN + n0;

    auto issue_B = [&](int kc, int soff) {
#pragma unroll
        for (int h = 0; h < 8; h++) {
            int idx = tid + h * 128;               // 1024 over 32 rows x 32 float4
            int k = idx >> 5, c4 = (idx & 31) * 4;
            const float* gp = Bx + (size_t)(kc * 32 + k) * HIDDEN + c4;
            cpa16(sb + soff + k * (BPITCH2 * 4) + c4 * 4, gp, 16);
        }
    };

    float acc[4][4][4] = {};

    issue_B(0, 0);
    cpa_commit();
    issue_B(1, G2_STAGE);
    cpa_commit();

    const int bfrag = tq * BPITCH2 + nw * 32 + g;

    const int NK = INTER / 32;
    int soff_c = 0, soff_p = 2 * G2_STAGE;
    for (int kc = 0; kc < NK; kc++) {
        if (kc + 1 < NK) cpa_wait1(); else cpa_wait0();
        __syncthreads();
        if (kc + 2 < NK) {
            issue_B(kc + 2, soff_p);
            cpa_commit();
        }

        const float* Bs = (const float*)(smem + soff_c);

#pragma unroll
        for (int kk = 0; kk < 4; kk++) {
            uint32_t bb[4][2];
#pragma unroll
            for (int ni = 0; ni < 4; ni++) {
                const float* bp = Bs + kk * (8 * BPITCH2) + bfrag + ni * 8;
                bb[ni][0] = f2tf(bp[0]); bb[ni][1] = f2tf(bp[4 * BPITCH2]);
            }
#pragma unroll
            for (int mi = 0; mi < 4; mi++) {
                const float4 av = *(const float4*)(ap + kk * 1024 + mi * 128);
                uint32_t a[4];
                a[0] = __float_as_uint(av.x);
                a[1] = __float_as_uint(av.y);
                a[2] = __float_as_uint(av.z);
                a[3] = __float_as_uint(av.w);
#pragma unroll
                for (int ni = 0; ni < 4; ni++)
                    mma8(acc[mi][ni], a, bb[ni][0], bb[ni][1]);
            }
        }
        ap += 4096;
        soff_c += G2_STAGE; if (soff_c == NSTAGE * G2_STAGE) soff_c = 0;
        soff_p += G2_STAGE; if (soff_p == NSTAGE * G2_STAGE) soff_p = 0;
    }

#pragma unroll
    for (int mi = 0; mi < 4; mi++) {
        int t0 = tokS[mi * 16 + g], t1 = tokS[mi * 16 + g + 8];
#pragma unroll
        for (int ni = 0; ni < 4; ni++) {
            int col = n0 + nw * 32 + ni * 8 + 2 * tq;
            if (t0 >= 0)
                *(float2*)(out + (size_t)t0 * HIDDEN + col) =
                    make_float2(acc[mi][ni][0], acc[mi][ni][1]);
            if (t1 >= 0)
                *(float2*)(out + (size_t)t1 * HIDDEN + col) =
                    make_float2(acc[mi][ni][2], acc[mi][ni][3]);
        }
    }
}

// ---------------- launch ----------------
extern "C" void kernel_launch(void* const* d_in, const int* in_sizes, int n_in,
                              void* d_out, int out_size) {
    const float* x    = (const float*)d_in[0];
    const int*   tids = (const int*)d_in[1];
    const float* gup  = (const float*)d_in[2];
    const float* down = (const float*)d_in[3];
    float*       out  = (float*)d_out;

    cudaFuncSetAttribute(pack_x_kernel, cudaFuncAttributeMaxDynamicSharedMemorySize, PX_SMEM);
    cudaFuncSetAttribute(gemm1_tc, cudaFuncAttributeMaxDynamicSharedMemorySize, G1_SMEM);
    cudaFuncSetAttribute(gemm2_tc, cudaFuncAttributeMaxDynamicSharedMemorySize, G2_SMEM);

    detect_kernel<<<1, 32>>>(tids);
    route_kernel<<<NUM_TOKENS / 256, 256>>>(tids);

    pack_x_kernel<<<dim3(HIDDEN / 128, MAX_TILES), 256, PX_SMEM>>>(x);
    gemm1_tc<<<dim3(MAX_TILES * 2, INTER / 64), 128, G1_SMEM>>>(gup);
    gemm2_tc<<<dim3(MAX_TILES * 2, HIDDEN / 128), 128, G2_SMEM>>>(down, out);
}

// round 12
// speedup vs baseline: 1.1208x; 1.1208x over previous
#include <cuda_runtime.h>
#include <cstdint>

#define NUM_TOKENS 8192
#define HIDDEN 4096
#define NUM_EXPERTS 8
#define INTER 2048
#define GU_COLS 4096
#define MAX_TILES 72
#define NSTAGE 3

// ---------------- scratch ----------------
__device__ int g_counts[NUM_EXPERTS];
__device__ int g_lists[NUM_EXPERTS][NUM_TOKENS];
__device__ int g_is64;
// fragment-packed activations: [tile128][kfrag][mfrag 8][128 floats]
__device__ float g_xpack[(size_t)MAX_TILES * (HIDDEN / 8) * 8 * 128];
__device__ float g_interp[(size_t)MAX_TILES * (INTER / 8) * 8 * 128];

// ---------------- helpers ----------------
__device__ __forceinline__ uint32_t f2tf(float f) {
    uint32_t r;
    asm("cvt.rna.tf32.f32 %0, %1;" : "=r"(r) : "f"(f));
    return r;
}
__device__ __forceinline__ float4 cvt4(float4 v) {
    float4 r;
    r.x = __uint_as_float(f2tf(v.x));
    r.y = __uint_as_float(f2tf(v.y));
    r.z = __uint_as_float(f2tf(v.z));
    r.w = __uint_as_float(f2tf(v.w));
    return r;
}
__device__ __forceinline__ uint32_t smem_u32(const void* p) {
    uint32_t a;
    asm("{ .reg .u64 t; cvta.to.shared.u64 t, %1; cvt.u32.u64 %0, t; }" : "=r"(a) : "l"(p));
    return a;
}
__device__ __forceinline__ void mma8(float* d, const uint32_t* a, uint32_t b0, uint32_t b1) {
    asm volatile(
        "mma.sync.aligned.m16n8k8.row.col.f32.tf32.tf32.f32 "
        "{%0,%1,%2,%3},{%4,%5,%6,%7},{%8,%9},{%0,%1,%2,%3};"
        : "+f"(d[0]), "+f"(d[1]), "+f"(d[2]), "+f"(d[3])
        : "r"(a[0]), "r"(a[1]), "r"(a[2]), "r"(a[3]), "r"(b0), "r"(b1));
}
__device__ __forceinline__ void cpa16(uint32_t dst, const void* src) {
    asm volatile("cp.async.cg.shared.global [%0], [%1], 16;" :: "r"(dst), "l"(src));
}
__device__ __forceinline__ void cpa_commit() { asm volatile("cp.async.commit_group;" ::: "memory"); }
__device__ __forceinline__ void cpa_wait1()  { asm volatile("cp.async.wait_group 1;" ::: "memory"); }
__device__ __forceinline__ void cpa_wait0()  { asm volatile("cp.async.wait_group 0;" ::: "memory"); }

__device__ __forceinline__ float silu(float g) { return g / (1.0f + __expf(-g)); }

__device__ __forceinline__ int find_tile(int t, int* e_out, int* m0_out, int* cnt_out) {
    int acc = 0;
#pragma unroll
    for (int e = 0; e < NUM_EXPERTS; e++) {
        int c = g_counts[e];
        int nt = (c + 127) >> 7;
        if (t < acc + nt) { *e_out = e; *m0_out = (t - acc) << 7; *cnt_out = c; return 1; }
        acc += nt;
    }
    return 0;
}

// ---------------- routing ----------------
__global__ void detect_kernel(const int* __restrict__ t32) {
    if (threadIdx.x == 0) {
        int all_zero = 1;
        for (int i = 0; i < 256; i++) {
            int idx = 2 * (i * (NUM_TOKENS / 256)) + 1;
            if (t32[idx] != 0) { all_zero = 0; break; }
        }
        g_is64 = all_zero;
    }
    if (threadIdx.x < NUM_EXPERTS) g_counts[threadIdx.x] = 0;
}

__global__ void route_kernel(const int* __restrict__ t32) {
    int i = blockIdx.x * blockDim.x + threadIdx.x;
    if (i < NUM_TOKENS) {
        int v = g_is64 ? t32[2 * i] : t32[i];
        int e = v & 7;
        int p = atomicAdd(&g_counts[e], 1);
        g_lists[e][p] = i;
    }
}

// ---------------- pack_x: gather routed tokens -> tf32 fragment layout ----------------
#define PX_PITCH 132
#define PX_SMEM (128 * PX_PITCH * 4 + 512)
__global__ __launch_bounds__(256) void pack_x_kernel(const float* __restrict__ x) {
    extern __shared__ char smem[];
    int e, m0, count;
    if (!find_tile(blockIdx.y, &e, &m0, &count)) return;
    const int kb = blockIdx.x;
    const int tid = threadIdx.x;
    int* tokS = (int*)smem;
    float* tile = (float*)(smem + 512);
    if (tid < 128) tokS[tid] = (m0 + tid < count) ? g_lists[e][m0 + tid] : -1;
    __syncthreads();
#pragma unroll
    for (int j = 0; j < 16; j++) {
        int idx = tid + j * 256;
        int r = idx >> 5, c4 = (idx & 31) * 4;
        int t = tokS[r];
        float4 v = make_float4(0.f, 0.f, 0.f, 0.f);
        if (t >= 0) v = *(const float4*)(x + (size_t)t * HIDDEN + kb * 128 + c4);
        *(float4*)(tile + r * PX_PITCH + c4) = cvt4(v);
    }
    __syncthreads();
    const int lane = tid & 31, w = tid >> 5;
    const int g = lane >> 2, tq = lane & 3;
#pragma unroll
    for (int i = 0; i < 16; i++) {
        int f = w * 16 + i;
        int mf = f & 7, kfl = f >> 3;
        const float* src = tile + (mf * 16 + g) * PX_PITCH + kfl * 8 + tq;
        float4 o;
        o.x = src[0];
        o.y = src[8 * PX_PITCH];
        o.z = src[4];
        o.w = src[8 * PX_PITCH + 4];
        size_t off = (((size_t)blockIdx.y * (HIDDEN / 8) + kb * 16 + kfl) * 8 + mf) * 128 + lane * 4;
        *(float4*)(g_xpack + off) = o;
    }
}

// smem geometry: B-only ring, BK=64
#define BPITCH 72
#define BPITCH2 136
#define B1T_BYTES (64 * BPITCH * 4)       /* 18432: one 64x64 tile */
#define G1_STAGE (2 * B1T_BYTES)          /* 36864: gate + up */
#define G2_STAGE (64 * BPITCH2 * 4)       /* 34816: 64x128 tile */
#define G1_SMEM (NSTAGE * G1_STAGE)       /* 110592 */
#define G2_SMEM (NSTAGE * G2_STAGE)       /* 104448 */

// ---------------- GEMM1: Xpack(LDG) @ GU(smem) -> silu(gate)*up -> g_interp ----------------
// 256 threads, warps 2m x 4n, BM=128, BN=64, BK=64.
__global__ __launch_bounds__(256, 2) void gemm1_tc(const float* __restrict__ gup) {
    extern __shared__ char smem[];
    int e, m0, count;
    if (!find_tile(blockIdx.y, &e, &m0, &count)) return;
    const int n0 = blockIdx.x * 64;
    const int t_id = blockIdx.y;

    const uint32_t sb = smem_u32(smem);
    const int tid = threadIdx.x;
    const int wid = tid >> 5, lane = tid & 31;
    const int mw = wid >> 2, nw = wid & 3;
    const int g = lane >> 2, tq = lane & 3;

    // A: packed tf32 fragments via direct LDG.128 (L1-dedup across the 4 nw warps)
    const float* ap = g_xpack + (size_t)t_id * (HIDDEN / 8) * 1024
                              + (mw * 4) * 128 + lane * 4;
    const float* Bx = gup + (size_t)e * HIDDEN * GU_COLS + n0;

    auto issue_B = [&](int kc, int soff) {
#pragma unroll
        for (int h = 0; h < 4; h++) {
            int idx = tid + h * 256;               // 1024 over 64 rows x 16 float4
            int k = idx >> 4, n16 = (idx & 15) * 16;
            const float* gp = Bx + (size_t)(kc * 64 + k) * GU_COLS + (idx & 15) * 4;
            uint32_t base = sb + soff + k * (BPITCH * 4) + n16;
            cpa16(base, gp);
            cpa16(base + B1T_BYTES, gp + INTER);
        }
    };

    float accg[4][2][4] = {};
    float accu[4][2][4] = {};

    issue_B(0, 0);
    cpa_commit();
    issue_B(1, G1_STAGE);
    cpa_commit();

    const int bfrag = tq * BPITCH + nw * 16 + g;

    const int NK = HIDDEN / 64;                    // 64 iterations
    int soff_c = 0, soff_p = 2 * G1_STAGE;
    for (int kc = 0; kc < NK; kc++) {
        if (kc + 1 < NK) cpa_wait1(); else cpa_wait0();
        __syncthreads();
        if (kc + 2 < NK) {
            issue_B(kc + 2, soff_p);
            cpa_commit();
        }

        const float* Bg = (const float*)(smem + soff_c);
        const float* Bu = Bg + 64 * BPITCH;

#pragma unroll
        for (int kk = 0; kk < 8; kk++) {
            uint32_t bg[2][2], bu[2][2];
#pragma unroll
            for (int ni = 0; ni < 2; ni++) {
                const float* bp = Bg + kk * (8 * BPITCH) + bfrag + ni * 8;
                bg[ni][0] = f2tf(bp[0]); bg[ni][1] = f2tf(bp[4 * BPITCH]);
                const float* up = Bu + kk * (8 * BPITCH) + bfrag + ni * 8;
                bu[ni][0] = f2tf(up[0]); bu[ni][1] = f2tf(up[4 * BPITCH]);
            }
#pragma unroll
            for (int mi = 0; mi < 4; mi++) {
                const float4 av = *(const float4*)(ap + kk * 1024 + mi * 128);
                uint32_t a[4];
                a[0] = __float_as_uint(av.x);
                a[1] = __float_as_uint(av.y);
                a[2] = __float_as_uint(av.z);
                a[3] = __float_as_uint(av.w);
                mma8(accg[mi][0], a, bg[0][0], bg[0][1]);
                mma8(accg[mi][1], a, bg[1][0], bg[1][1]);
                mma8(accu[mi][0], a, bu[0][0], bu[0][1]);
                mma8(accu[mi][1], a, bu[1][0], bu[1][1]);
            }
        }
        ap += 8192;                                // 8 kfrags * 1024
        soff_c += G1_STAGE; if (soff_c == NSTAGE * G1_STAGE) soff_c = 0;
        soff_p += G1_STAGE; if (soff_p == NSTAGE * G1_STAGE) soff_p = 0;
    }

    // fused epilogue -> fragment-packed g_interp (pad rows are zeros; no guard needed)
#pragma unroll
    for (int mi = 0; mi < 4; mi++) {
        int mf = mw * 4 + mi;
#pragma unroll
        for (int ni = 0; ni < 2; ni++) {
            int c = nw * 16 + ni * 8 + 2 * tq;
            int kf = (n0 + c) >> 3;
            int hc2 = ((c >> 2) & 1) * 2;
            int tq0 = c & 3;
            float* base = g_interp + (((size_t)t_id * (INTER / 8) + kf) * 8 + mf) * 128;
            base[(g * 4 + tq0) * 4 + hc2] =
                __uint_as_float(f2tf(silu(accg[mi][ni][0]) * accu[mi][ni][0]));
            base[(g * 4 + tq0 + 1) * 4 + hc2] =
                __uint_as_float(f2tf(silu(accg[mi][ni][1]) * accu[mi][ni][1]));
            base[(g * 4 + tq0) * 4 + 1 + hc2] =
                __uint_as_float(f2tf(silu(accg[mi][ni][2]) * accu[mi][ni][2]));
            base[(g * 4 + tq0 + 1) * 4 + 1 + hc2] =
                __uint_as_float(f2tf(silu(accg[mi][ni][3]) * accu[mi][ni][3]));
        }
    }
}

// ---------------- GEMM2: g_interp(LDG) @ down(smem) -> out  (BM=128, BN=128, BK=64) ----------------
__global__ __launch_bounds__(256, 2) void gemm2_tc(const float* __restrict__ down,
                                                   float* __restrict__ out) {
    extern __shared__ char smem[];
    __shared__ int tokS[128];
    int e, m0, count;
    if (!find_tile(blockIdx.y, &e, &m0, &count)) return;
    const int n0 = blockIdx.x * 128;
    const int t_id = blockIdx.y;

    const uint32_t sb = smem_u32(smem);
    const int tid = threadIdx.x;
    const int wid = tid >> 5, lane = tid & 31;
    const int mw = wid >> 2, nw = wid & 3;
    const int g = lane >> 2, tq = lane & 3;

    if (tid < 128) tokS[tid] = (m0 + tid < count) ? g_lists[e][m0 + tid] : -1;
    __syncthreads();

    const float* ap = g_interp + (size_t)t_id * (INTER / 8) * 1024
                               + (mw * 4) * 128 + lane * 4;
    const float* Bx = down + (size_t)e * INTER * HIDDEN + n0;

    auto issue_B = [&](int kc, int soff) {
#pragma unroll
        for (int h = 0; h < 8; h++) {
            int idx = tid + h * 256;               // 2048 over 64 rows x 32 float4
            int k = idx >> 5, c4 = (idx & 31) * 4;
            const float* gp = Bx + (size_t)(kc * 64 + k) * HIDDEN + c4;
            cpa16(sb + soff + k * (BPITCH2 * 4) + c4 * 4, gp);
        }
    };

    float acc[4][4][4] = {};

    issue_B(0, 0);
    cpa_commit();
    issue_B(1, G2_STAGE);
    cpa_commit();

    const int bfrag = tq * BPITCH2 + nw * 32 + g;

    const int NK = INTER / 64;                     // 32 iterations
    int soff_c = 0, soff_p = 2 * G2_STAGE;
    for (int kc = 0; kc < NK; kc++) {
        if (kc + 1 < NK) cpa_wait1(); else cpa_wait0();
        __syncthreads();
        if (kc + 2 < NK) {
            issue_B(kc + 2, soff_p);
            cpa_commit();
        }

        const float* Bs = (const float*)(smem + soff_c);

#pragma unroll
        for (int kk = 0; kk < 8; kk++) {
            uint32_t bb[4][2];
#pragma unroll
            for (int ni = 0; ni < 4; ni++) {
                const float* bp = Bs + kk * (8 * BPITCH2) + bfrag + ni * 8;
                bb[ni][0] = f2tf(bp[0]); bb[ni][1] = f2tf(bp[4 * BPITCH2]);
            }
#pragma unroll
            for (int mi = 0; mi < 4; mi++) {
                const float4 av = *(const float4*)(ap + kk * 1024 + mi * 128);
                uint32_t a[4];
                a[0] = __float_as_uint(av.x);
                a[1] = __float_as_uint(av.y);
                a[2] = __float_as_uint(av.z);
                a[3] = __float_as_uint(av.w);
#pragma unroll
                for (int ni = 0; ni < 4; ni++)
                    mma8(acc[mi][ni], a, bb[ni][0], bb[ni][1]);
            }
        }
        ap += 8192;
        soff_c += G2_STAGE; if (soff_c == NSTAGE * G2_STAGE) soff_c = 0;
        soff_p += G2_STAGE; if (soff_p == NSTAGE * G2_STAGE) soff_p = 0;
    }

#pragma unroll
    for (int mi = 0; mi < 4; mi++) {
        int r0 = mw * 64 + mi * 16 + g;
        int t0 = tokS[r0], t1 = tokS[r0 + 8];
#pragma unroll
        for (int ni = 0; ni < 4; ni++) {
            int col = n0 + nw * 32 + ni * 8 + 2 * tq;
            if (t0 >= 0)
                *(float2*)(out + (size_t)t0 * HIDDEN + col) =
                    make_float2(acc[mi][ni][0], acc[mi][ni][1]);
            if (t1 >= 0)
                *(float2*)(out + (size_t)t1 * HIDDEN + col) =
                    make_float2(acc[mi][ni][2], acc[mi][ni][3]);
        }
    }
}

// ---------------- launch ----------------
extern "C" void kernel_launch(void* const* d_in, const int* in_sizes, int n_in,
                              void* d_out, int out_size) {
    const float* x    = (const float*)d_in[0];
    const int*   tids = (const int*)d_in[1];
    const float* gup  = (const float*)d_in[2];
    const float* down = (const float*)d_in[3];
    float*       out  = (float*)d_out;

    cudaFuncSetAttribute(pack_x_kernel, cudaFuncAttributeMaxDynamicSharedMemorySize, PX_SMEM);
    cudaFuncSetAttribute(gemm1_tc, cudaFuncAttributeMaxDynamicSharedMemorySize, G1_SMEM);
    cudaFuncSetAttribute(gemm2_tc, cudaFuncAttributeMaxDynamicSharedMemorySize, G2_SMEM);

    detect_kernel<<<1, 32>>>(tids);
    route_kernel<<<NUM_TOKENS / 256, 256>>>(tids);

    pack_x_kernel<<<dim3(HIDDEN / 128, MAX_TILES), 256, PX_SMEM>>>(x);
    gemm1_tc<<<dim3(INTER / 64, MAX_TILES), 256, G1_SMEM>>>(gup);
    gemm2_tc<<<dim3(HIDDEN / 128, MAX_TILES), 256, G2_SMEM>>>(down, out);
}

// round 13
// speedup vs baseline: 2.6069x; 2.3259x over previous
#include <cuda_runtime.h>
#include <cuda_fp16.h>
#include <cstdint>

#define NUM_TOKENS 8192
#define HIDDEN 4096
#define NUM_EXPERTS 8
#define INTER 2048
#define GU_COLS 4096
#define MAX_TILES 72
#define NSTAGE 3

// ---------------- scratch ----------------
__device__ int g_counts[NUM_EXPERTS];
__device__ int g_lists[NUM_EXPERTS][NUM_TOKENS];
__device__ int g_is64;
// fp16 A-fragment packed activations: [tile][kf16][mf 8][lane 32][4 b32]
__device__ uint32_t g_xpackh[(size_t)MAX_TILES * (HIDDEN / 16) * 8 * 32 * 4];   // 75.5 MB
__device__ uint32_t g_interph[(size_t)MAX_TILES * (INTER / 16) * 8 * 32 * 4];   // 37.7 MB
// fp16 B-fragment packed weights
// wp1: [e][nt64 32][kf16 256][gu 2][nf 8][lane 32][2 b32]  (268 MB)
__device__ uint32_t g_wp1[(size_t)NUM_EXPERTS * 32 * 256 * 2 * 8 * 32 * 2];
// wp2: [e][nt128 32][kf16 128][nf 16][lane 32][2 b32]      (134 MB)
__device__ uint32_t g_wp2[(size_t)NUM_EXPERTS * 32 * 128 * 16 * 32 * 2];

// ---------------- helpers ----------------
__device__ __forceinline__ uint32_t smem_u32(const void* p) {
    uint32_t a;
    asm("{ .reg .u64 t; cvta.to.shared.u64 t, %1; cvt.u32.u64 %0, t; }" : "=r"(a) : "l"(p));
    return a;
}
__device__ __forceinline__ uint32_t f2h2(float lo, float hi) {
    __half2 h = __floats2half2_rn(lo, hi);
    return *(uint32_t*)&h;
}
__device__ __forceinline__ void mma16(float* d, const uint32_t* a, uint32_t b0, uint32_t b1) {
    asm volatile(
        "mma.sync.aligned.m16n8k16.row.col.f32.f16.f16.f32 "
        "{%0,%1,%2,%3},{%4,%5,%6,%7},{%8,%9},{%0,%1,%2,%3};"
        : "+f"(d[0]), "+f"(d[1]), "+f"(d[2]), "+f"(d[3])
        : "r"(a[0]), "r"(a[1]), "r"(a[2]), "r"(a[3]), "r"(b0), "r"(b1));
}
__device__ __forceinline__ void cpa16(uint32_t dst, const void* src) {
    asm volatile("cp.async.cg.shared.global [%0], [%1], 16;" :: "r"(dst), "l"(src));
}
__device__ __forceinline__ void cpa_commit() { asm volatile("cp.async.commit_group;" ::: "memory"); }
__device__ __forceinline__ void cpa_wait1()  { asm volatile("cp.async.wait_group 1;" ::: "memory"); }
__device__ __forceinline__ void cpa_wait0()  { asm volatile("cp.async.wait_group 0;" ::: "memory"); }

__device__ __forceinline__ float silu(float g) { return g / (1.0f + __expf(-g)); }

__device__ __forceinline__ int find_tile(int t, int* e_out, int* m0_out, int* cnt_out) {
    int acc = 0;
#pragma unroll
    for (int e = 0; e < NUM_EXPERTS; e++) {
        int c = g_counts[e];
        int nt = (c + 127) >> 7;
        if (t < acc + nt) { *e_out = e; *m0_out = (t - acc) << 7; *cnt_out = c; return 1; }
        acc += nt;
    }
    return 0;
}

// ---------------- routing ----------------
__global__ void detect_kernel(const int* __restrict__ t32) {
    if (threadIdx.x == 0) {
        int all_zero = 1;
        for (int i = 0; i < 256; i++) {
            int idx = 2 * (i * (NUM_TOKENS / 256)) + 1;
            if (t32[idx] != 0) { all_zero = 0; break; }
        }
        g_is64 = all_zero;
    }
    if (threadIdx.x < NUM_EXPERTS) g_counts[threadIdx.x] = 0;
}

__global__ void route_kernel(const int* __restrict__ t32) {
    int i = blockIdx.x * blockDim.x + threadIdx.x;
    if (i < NUM_TOKENS) {
        int v = g_is64 ? t32[2 * i] : t32[i];
        int e = v & 7;
        int p = atomicAdd(&g_counts[e], 1);
        g_lists[e][p] = i;
    }
}

// ---------------- pack_x: gather routed tokens -> fp16 A-fragment layout ----------------
#define PX_PITCH 132
#define PX_SMEM (128 * PX_PITCH * 4 + 512)
__global__ __launch_bounds__(256) void pack_x_kernel(const float* __restrict__ x) {
    extern __shared__ char smem[];
    int e, m0, count;
    if (!find_tile(blockIdx.y, &e, &m0, &count)) return;
    const int kb = blockIdx.x;             // 128-col block -> 8 kf16
    const int tid = threadIdx.x;
    int* tokS = (int*)smem;
    float* tile = (float*)(smem + 512);
    if (tid < 128) tokS[tid] = (m0 + tid < count) ? g_lists[e][m0 + tid] : -1;
    __syncthreads();
#pragma unroll
    for (int j = 0; j < 16; j++) {
        int idx = tid + j * 256;
        int r = idx >> 5, c4 = (idx & 31) * 4;
        int t = tokS[r];
        float4 v = make_float4(0.f, 0.f, 0.f, 0.f);
        if (t >= 0) v = *(const float4*)(x + (size_t)t * HIDDEN + kb * 128 + c4);
        *(float4*)(tile + r * PX_PITCH + c4) = v;
    }
    __syncthreads();
    const int lane = tid & 31, w = tid >> 5;
    const int g = lane >> 2, tq = lane & 3;
    const int kf = kb * 8 + w;
#pragma unroll
    for (int mf = 0; mf < 8; mf++) {
        int r0 = mf * 16 + g;
        int c0 = w * 16 + 2 * tq;
        float2 v00 = *(float2*)(tile + r0 * PX_PITCH + c0);
        float2 v10 = *(float2*)(tile + (r0 + 8) * PX_PITCH + c0);
        float2 v01 = *(float2*)(tile + r0 * PX_PITCH + c0 + 8);
        float2 v11 = *(float2*)(tile + (r0 + 8) * PX_PITCH + c0 + 8);
        uint4 o;
        o.x = f2h2(v00.x, v00.y);
        o.y = f2h2(v10.x, v10.y);
        o.z = f2h2(v01.x, v01.y);
        o.w = f2h2(v11.x, v11.y);
        size_t off = ((((size_t)blockIdx.y * (HIDDEN / 16) + kf) * 8 + mf) * 32 + lane) * 4;
        *(uint4*)(g_xpackh + off) = o;
    }
}

// ---------------- pack_w1: gup -> fp16 B-fragment layout ----------------
__global__ __launch_bounds__(256) void pack_w1_kernel(const float* __restrict__ gup) {
    const int e = blockIdx.z, nt = blockIdx.y;
    const int tid = threadIdx.x;
    const int w = tid >> 5, lane = tid & 31;
    const int g = lane >> 2, tq = lane & 3;
    const int kf = blockIdx.x * 8 + w;     // 0..255
    const float* W = gup + (size_t)e * HIDDEN * GU_COLS;
    const int k0 = kf * 16 + tq * 2;
#pragma unroll
    for (int i = 0; i < 16; i++) {
        int gu = i >> 3, nf = i & 7;
        int c = gu * INTER + nt * 64 + nf * 8 + g;
        const float* Wc = W + c;
        uint2 o;
        o.x = f2h2(Wc[(size_t)k0 * GU_COLS], Wc[(size_t)(k0 + 1) * GU_COLS]);
        o.y = f2h2(Wc[(size_t)(k0 + 8) * GU_COLS], Wc[(size_t)(k0 + 9) * GU_COLS]);
        size_t off = ((((((size_t)e * 32 + nt) * 256 + kf) * 2 + gu) * 8 + nf) * 32 + lane) * 2;
        *(uint2*)(g_wp1 + off) = o;
    }
}

// ---------------- pack_w2: down -> fp16 B-fragment layout ----------------
__global__ __launch_bounds__(256) void pack_w2_kernel(const float* __restrict__ down) {
    const int e = blockIdx.z, nt = blockIdx.y;
    const int tid = threadIdx.x;
    const int w = tid >> 5, lane = tid & 31;
    const int g = lane >> 2, tq = lane & 3;
    const int kf = blockIdx.x * 8 + w;     // 0..127
    const float* W = down + (size_t)e * INTER * HIDDEN;
    const int k0 = kf * 16 + tq * 2;
#pragma unroll
    for (int nf = 0; nf < 16; nf++) {
        int c = nt * 128 + nf * 8 + g;
        const float* Wc = W + c;
        uint2 o;
        o.x = f2h2(Wc[(size_t)k0 * HIDDEN], Wc[(size_t)(k0 + 1) * HIDDEN]);
        o.y = f2h2(Wc[(size_t)(k0 + 8) * HIDDEN], Wc[(size_t)(k0 + 9) * HIDDEN]);
        size_t off = (((((size_t)e * 32 + nt) * 128 + kf) * 16 + nf) * 32 + lane) * 2;
        *(uint2*)(g_wp2 + off) = o;
    }
}

// smem: per stage [A 16KB][B 16KB], BK=64 (4 kf16)
#define STAGE_BYTES 32768
#define GEMM_SMEM (NSTAGE * STAGE_BYTES)   /* 98304 */

// ---------------- GEMM1: Xpackh @ wp1 -> silu(gate)*up -> g_interph ----------------
// 256 thr, warps 2m x 4n, BM=128, BN=64, BK=64.
__global__ __launch_bounds__(256, 2) void gemm1_tc() {
    extern __shared__ char smem[];
    int e, m0, count;
    if (!find_tile(blockIdx.y, &e, &m0, &count)) return;
    const int nt = blockIdx.x;             // 64-col tile of INTER
    const int t_id = blockIdx.y;

    const uint32_t sb = smem_u32(smem);
    const int tid = threadIdx.x;
    const int wid = tid >> 5, lane = tid & 31;
    const int mw = wid >> 2, nw = wid & 3;
    const int g = lane >> 2, tq = lane & 3;

    const uint32_t* xA = g_xpackh + (size_t)t_id * (HIDDEN / 16) * 1024;
    const uint32_t* wB = g_wp1 + (((size_t)e * 32 + nt) * 256) * 1024;

    auto issue = [&](int kc, int soff) {
        const uint32_t* As = xA + (size_t)kc * 4096;
        const uint32_t* Bs = wB + (size_t)kc * 4096;
#pragma unroll
        for (int j = 0; j < 4; j++) {
            int idx = tid + j * 256;
            cpa16(sb + soff + idx * 16, As + idx * 4);
            cpa16(sb + soff + 16384 + idx * 16, Bs + idx * 4);
        }
    };

    float accg[4][2][4] = {};
    float accu[4][2][4] = {};

    issue(0, 0);
    cpa_commit();
    issue(1, STAGE_BYTES);
    cpa_commit();

    const int NK = HIDDEN / 64;            // 64 iterations
    int soff_c = 0, soff_p = 2 * STAGE_BYTES;
    for (int kc = 0; kc < NK; kc++) {
        if (kc + 1 < NK) cpa_wait1(); else cpa_wait0();
        __syncthreads();
        if (kc + 2 < NK) {
            issue(kc + 2, soff_p);
            cpa_commit();
        }

#pragma unroll
        for (int kk = 0; kk < 4; kk++) {
            uint2 bg[2], bu[2];
#pragma unroll
            for (int ni = 0; ni < 2; ni++) {
                bg[ni] = *(const uint2*)(smem + soff_c + 16384 +
                            ((kk * 2 + 0) * 8 + nw * 2 + ni) * 256 + lane * 8);
                bu[ni] = *(const uint2*)(smem + soff_c + 16384 +
                            ((kk * 2 + 1) * 8 + nw * 2 + ni) * 256 + lane * 8);
            }
#pragma unroll
            for (int mi = 0; mi < 4; mi++) {
                const uint4 a = *(const uint4*)(smem + soff_c +
                            ((kk * 8 + mw * 4 + mi) * 32 + lane) * 16);
                mma16(accg[mi][0], &a.x, bg[0].x, bg[0].y);
                mma16(accg[mi][1], &a.x, bg[1].x, bg[1].y);
                mma16(accu[mi][0], &a.x, bu[0].x, bu[0].y);
                mma16(accu[mi][1], &a.x, bu[1].x, bu[1].y);
            }
        }
        soff_c += STAGE_BYTES; if (soff_c == NSTAGE * STAGE_BYTES) soff_c = 0;
        soff_p += STAGE_BYTES; if (soff_p == NSTAGE * STAGE_BYTES) soff_p = 0;
    }

    // fused epilogue -> fp16 A-fragment g_interph. Cols nw*16..+15 = one kf; regs:
    // ni0 -> regs {0,1}, ni1 -> regs {2,3}; each thread writes one uint4 per mi.
    const int kf = nt * 4 + nw;            // (nt*64 + nw*16) / 16
#pragma unroll
    for (int mi = 0; mi < 4; mi++) {
        int mf = mw * 4 + mi;
        uint4 o;
        {
            float v0 = silu(accg[mi][0][0]) * accu[mi][0][0];
            float v1 = silu(accg[mi][0][1]) * accu[mi][0][1];
            float v2 = silu(accg[mi][0][2]) * accu[mi][0][2];
            float v3 = silu(accg[mi][0][3]) * accu[mi][0][3];
            o.x = f2h2(v0, v1);
            o.y = f2h2(v2, v3);
        }
        {
            float v0 = silu(accg[mi][1][0]) * accu[mi][1][0];
            float v1 = silu(accg[mi][1][1]) * accu[mi][1][1];
            float v2 = silu(accg[mi][1][2]) * accu[mi][1][2];
            float v3 = silu(accg[mi][1][3]) * accu[mi][1][3];
            o.z = f2h2(v0, v1);
            o.w = f2h2(v2, v3);
        }
        size_t off = ((((size_t)t_id * (INTER / 16) + kf) * 8 + mf) * 32 + (g * 4 + tq)) * 4;
        *(uint4*)(g_interph + off) = o;
    }
}

// ---------------- GEMM2: g_interph @ wp2 -> out  (BM=128, BN=128, BK=64) ----------------
__global__ __launch_bounds__(256, 2) void gemm2_tc(float* __restrict__ out) {
    extern __shared__ char smem[];
    __shared__ int tokS[128];
    int e, m0, count;
    if (!find_tile(blockIdx.y, &e, &m0, &count)) return;
    const int nt = blockIdx.x;             // 128-col tile of HIDDEN
    const int t_id = blockIdx.y;
    const int n0 = nt * 128;

    const uint32_t sb = smem_u32(smem);
    const int tid = threadIdx.x;
    const int wid = tid >> 5, lane = tid & 31;
    const int mw = wid >> 2, nw = wid & 3;
    const int g = lane >> 2, tq = lane & 3;

    if (tid < 128) tokS[tid] = (m0 + tid < count) ? g_lists[e][m0 + tid] : -1;
    __syncthreads();

    const uint32_t* xA = g_interph + (size_t)t_id * (INTER / 16) * 1024;
    const uint32_t* wB = g_wp2 + (((size_t)e * 32 + nt) * 128) * 1024;

    auto issue = [&](int kc, int soff) {
        const uint32_t* As = xA + (size_t)kc * 4096;
        const uint32_t* Bs = wB + (size_t)kc * 4096;
#pragma unroll
        for (int j = 0; j < 4; j++) {
            int idx = tid + j * 256;
            cpa16(sb + soff + idx * 16, As + idx * 4);
            cpa16(sb + soff + 16384 + idx * 16, Bs + idx * 4);
        }
    };

    float acc[4][4][4] = {};

    issue(0, 0);
    cpa_commit();
    issue(1, STAGE_BYTES);
    cpa_commit();

    const int NK = INTER / 64;             // 32 iterations
    int soff_c = 0, soff_p = 2 * STAGE_BYTES;
    for (int kc = 0; kc < NK; kc++) {
        if (kc + 1 < NK) cpa_wait1(); else cpa_wait0();
        __syncthreads();
        if (kc + 2 < NK) {
            issue(kc + 2, soff_p);
            cpa_commit();
        }

#pragma unroll
        for (int kk = 0; kk < 4; kk++) {
            uint2 bb[4];
#pragma unroll
            for (int ni = 0; ni < 4; ni++)
                bb[ni] = *(const uint2*)(smem + soff_c + 16384 +
                            (kk * 16 + nw * 4 + ni) * 256 + lane * 8);
#pragma unroll
            for (int mi = 0; mi < 4; mi++) {
                const uint4 a = *(const uint4*)(smem + soff_c +
                            ((kk * 8 + mw * 4 + mi) * 32 + lane) * 16);
#pragma unroll
                for (int ni = 0; ni < 4; ni++)
                    mma16(acc[mi][ni], &a.x, bb[ni].x, bb[ni].y);
            }
        }
        soff_c += STAGE_BYTES; if (soff_c == NSTAGE * STAGE_BYTES) soff_c = 0;
        soff_p += STAGE_BYTES; if (soff_p == NSTAGE * STAGE_BYTES) soff_p = 0;
    }

#pragma unroll
    for (int mi = 0; mi < 4; mi++) {
        int r0 = mw * 64 + mi * 16 + g;
        int t0 = tokS[r0], t1 = tokS[r0 + 8];
#pragma unroll
        for (int ni = 0; ni < 4; ni++) {
            int col = n0 + nw * 32 + ni * 8 + 2 * tq;
            if (t0 >= 0)
                *(float2*)(out + (size_t)t0 * HIDDEN + col) =
                    make_float2(acc[mi][ni][0], acc[mi][ni][1]);
            if (t1 >= 0)
                *(float2*)(out + (size_t)t1 * HIDDEN + col) =
                    make_float2(acc[mi][ni][2], acc[mi][ni][3]);
        }
    }
}

// ---------------- launch ----------------
extern "C" void kernel_launch(void* const* d_in, const int* in_sizes, int n_in,
                              void* d_out, int out_size) {
    const float* x    = (const float*)d_in[0];
    const int*   tids = (const int*)d_in[1];
    const float* gup  = (const float*)d_in[2];
    const float* down = (const float*)d_in[3];
    float*       out  = (float*)d_out;

    cudaFuncSetAttribute(pack_x_kernel, cudaFuncAttributeMaxDynamicSharedMemorySize, PX_SMEM);
    cudaFuncSetAttribute(gemm1_tc, cudaFuncAttributeMaxDynamicSharedMemorySize, GEMM_SMEM);
    cudaFuncSetAttribute(gemm2_tc, cudaFuncAttributeMaxDynamicSharedMemorySize, GEMM_SMEM);

    detect_kernel<<<1, 32>>>(tids);
    route_kernel<<<NUM_TOKENS / 256, 256>>>(tids);

    pack_w1_kernel<<<dim3(32, 32, NUM_EXPERTS), 256>>>(gup);
    pack_w2_kernel<<<dim3(16, 32, NUM_EXPERTS), 256>>>(down);
    pack_x_kernel<<<dim3(HIDDEN / 128, MAX_TILES), 256, PX_SMEM>>>(x);

    gemm1_tc<<<dim3(INTER / 64, MAX_TILES), 256, GEMM_SMEM>>>();
    gemm2_tc<<<dim3(HIDDEN / 128, MAX_TILES), 256, GEMM_SMEM>>>(out);
}